// round 17
// baseline (speedup 1.0000x reference)
#include <cuda_runtime.h>
#include <cuda_bf16.h>
#include <math.h>

// Problem constants
#define N_TOK   32768      // 32 * 32 * 32
#define N_E     1024
#define E_DIM   64
#define N_ELEM  2097152    // 32*64*32*32
#define HW      1024
#define BETA    0.25f
#define DECAY   0.99f
#define EPSF    1e-5f

// Output layout (flattened reference tuple, float32)
#define O_LOSS   0
#define O_ZQ     1
#define O_PERP   (1 + N_ELEM)
#define O_MINENC (2 + N_ELEM)
#define O_IDX    (2 + N_ELEM + (size_t)N_TOK*N_E)

// Scratch (no allocations allowed -> device globals)
__device__ int   g_idx[N_TOK];
__device__ float g_enorm[N_E];
__device__ float g_cs[N_E];
__device__ float g_sum[N_E * E_DIM];
__device__ float g_loss_acc;
__device__ unsigned int g_done;

// ---- packed f32x2 helpers (semantics identical to 2x scalar FFMA per lane) ----
#define FMA2(d, a, b, c) \
    asm("fma.rn.f32x2 %0, %1, %2, %3;" : "=l"(d) : "l"(a), "l"(b), "l"(c))
#define UNPACK2(lo, hi, v) \
    asm("mov.b64 {%0, %1}, %2;" : "=f"(lo), "=f"(hi) : "l"(v))
#define PACK2(v, lo, hi) \
    asm("mov.b64 %0, {%1, %2};" : "=l"(v) : "f"(lo), "f"(hi))
#define LDSV2(e01, e23, base, OFF) \
    asm("ld.shared.v2.u64 {%0, %1}, [%2+" #OFF "];" \
        : "=l"(e01), "=l"(e23) : "r"(base))

// ---------------------------------------------------------------------------
// Kernel 0: codebook norms + zero scratch
// ---------------------------------------------------------------------------
__global__ void k_prep(const float* __restrict__ emb) {
    int j = blockIdx.x * 256 + threadIdx.x;
    if (j < N_E) {
        const float* e = emb + j * E_DIM;
        float s0 = 0.f, s1 = 0.f, s2 = 0.f, s3 = 0.f;
        #pragma unroll
        for (int c = 0; c < E_DIM; c += 4) {
            s0 = __fmaf_rn(e[c+0], e[c+0], s0);
            s1 = __fmaf_rn(e[c+1], e[c+1], s1);
            s2 = __fmaf_rn(e[c+2], e[c+2], s2);
            s3 = __fmaf_rn(e[c+3], e[c+3], s3);
        }
        g_enorm[j] = __fadd_rn(__fadd_rn(s0, s1), __fadd_rn(s2, s3));
        g_cs[j] = 0.f;
        float4 z4 = make_float4(0.f, 0.f, 0.f, 0.f);
        float4* s = reinterpret_cast<float4*>(g_sum + j * E_DIM);
        #pragma unroll
        for (int c = 0; c < E_DIM / 4; ++c) s[c] = z4;
        if (j == 0) { g_loss_acc = 0.f; g_done = 0u; }
    }
}

// ---------------------------------------------------------------------------
// Kernel 1: per-token argmin (bit-identical to the passing 202.8 kernel)
// ---------------------------------------------------------------------------
#define ST 68

__global__ __launch_bounds__(128, 2)
void k_argmin(const float* __restrict__ z,
              const float* __restrict__ emb,
              float* __restrict__ out) {
    __shared__ __align__(16) float tile[64 * ST];
    __shared__ float sn[64];

    const int t   = threadIdx.x;
    const int n0  = blockIdx.x * 128;
    const int b   = n0 >> 10;
    const int hw0 = n0 & 1023;
    const float* zb = z + (size_t)b * E_DIM * HW;

    float4 zr[16];
    #pragma unroll
    for (int g = 0; g < 2; ++g) {
        __syncthreads();
        #pragma unroll
        for (int k = 0; k < 32; ++k) {
            int c = k * 2 + (t >> 6);
            int i = t & 63;
            tile[i * ST + c] = zb[c * HW + hw0 + g * 64 + i];
        }
        __syncthreads();
        if ((t >> 6) == g) {
            int local = t & 63;
            #pragma unroll
            for (int q = 0; q < 16; ++q)
                zr[q] = *reinterpret_cast<const float4*>(&tile[local * ST + 4 * q]);
        }
    }

    unsigned long long zp[32];
    #pragma unroll
    for (int q = 0; q < 16; ++q) {
        PACK2(zp[2*q+0], zr[q].x, zr[q].y);
        PACK2(zp[2*q+1], zr[q].z, zr[q].w);
    }

    float zn;
    {
        unsigned long long na = 0ull, nb = 0ull;
        #pragma unroll
        for (int q = 0; q < 16; ++q) {
            FMA2(na, zp[2*q+0], zp[2*q+0], na);
            FMA2(nb, zp[2*q+1], zp[2*q+1], nb);
        }
        float a0, a1, a2, a3;
        UNPACK2(a0, a1, na);
        UNPACK2(a2, a3, nb);
        zn = __fadd_rn(__fadd_rn(a0, a1), __fadd_rn(a2, a3));
    }

    float best = 3.4e38f;
    int bestIdx = 0;
    const unsigned tbase = (unsigned)__cvta_generic_to_shared(tile);

    for (int tile0 = 0; tile0 < N_E; tile0 += 64) {
        __syncthreads();
        #pragma unroll
        for (int k = 0; k < 32; ++k) {
            int j = k * 2 + (t >> 6);
            int c = t & 63;
            tile[j * ST + c] = emb[(tile0 + j) * E_DIM + c];
        }
        if (t < 64) sn[t] = g_enorm[tile0 + t];
        __syncthreads();

        #pragma unroll 4
        for (int j = 0; j < 64; ++j) {
            const unsigned rowa = tbase + (unsigned)(j * (ST * 4));
            unsigned long long acc_a = 0ull, acc_b = 0ull;
            unsigned long long e01, e23;
            LDSV2(e01, e23, rowa,   0); FMA2(acc_a, zp[ 0], e01, acc_a); FMA2(acc_b, zp[ 1], e23, acc_b);
            LDSV2(e01, e23, rowa,  16); FMA2(acc_a, zp[ 2], e01, acc_a); FMA2(acc_b, zp[ 3], e23, acc_b);
            LDSV2(e01, e23, rowa,  32); FMA2(acc_a, zp[ 4], e01, acc_a); FMA2(acc_b, zp[ 5], e23, acc_b);
            LDSV2(e01, e23, rowa,  48); FMA2(acc_a, zp[ 6], e01, acc_a); FMA2(acc_b, zp[ 7], e23, acc_b);
            LDSV2(e01, e23, rowa,  64); FMA2(acc_a, zp[ 8], e01, acc_a); FMA2(acc_b, zp[ 9], e23, acc_b);
            LDSV2(e01, e23, rowa,  80); FMA2(acc_a, zp[10], e01, acc_a); FMA2(acc_b, zp[11], e23, acc_b);
            LDSV2(e01, e23, rowa,  96); FMA2(acc_a, zp[12], e01, acc_a); FMA2(acc_b, zp[13], e23, acc_b);
            LDSV2(e01, e23, rowa, 112); FMA2(acc_a, zp[14], e01, acc_a); FMA2(acc_b, zp[15], e23, acc_b);
            LDSV2(e01, e23, rowa, 128); FMA2(acc_a, zp[16], e01, acc_a); FMA2(acc_b, zp[17], e23, acc_b);
            LDSV2(e01, e23, rowa, 144); FMA2(acc_a, zp[18], e01, acc_a); FMA2(acc_b, zp[19], e23, acc_b);
            LDSV2(e01, e23, rowa, 160); FMA2(acc_a, zp[20], e01, acc_a); FMA2(acc_b, zp[21], e23, acc_b);
            LDSV2(e01, e23, rowa, 176); FMA2(acc_a, zp[22], e01, acc_a); FMA2(acc_b, zp[23], e23, acc_b);
            LDSV2(e01, e23, rowa, 192); FMA2(acc_a, zp[24], e01, acc_a); FMA2(acc_b, zp[25], e23, acc_b);
            LDSV2(e01, e23, rowa, 208); FMA2(acc_a, zp[26], e01, acc_a); FMA2(acc_b, zp[27], e23, acc_b);
            LDSV2(e01, e23, rowa, 224); FMA2(acc_a, zp[28], e01, acc_a); FMA2(acc_b, zp[29], e23, acc_b);
            LDSV2(e01, e23, rowa, 240); FMA2(acc_a, zp[30], e01, acc_a); FMA2(acc_b, zp[31], e23, acc_b);

            float d0, d1, d2, d3;
            UNPACK2(d0, d1, acc_a);
            UNPACK2(d2, d3, acc_b);
            float dot = __fadd_rn(__fadd_rn(d0, d1), __fadd_rn(d2, d3));
            float dval = __fadd_rn(__fadd_rn(zn, sn[j]), -__fmul_rn(2.0f, dot));
            if (dval < best) { best = dval; bestIdx = tile0 + j; }
        }
    }

    const int n = n0 + t;
    g_idx[n] = bestIdx;
    out[O_IDX + n] = (float)bestIdx;

    atomicAdd(&g_cs[bestIdx], 1.0f);
    float* s = g_sum + bestIdx * E_DIM;
    #pragma unroll
    for (int q = 0; q < 32; ++q) {
        float lo, hi;
        UNPACK2(lo, hi, zp[q]);
        atomicAdd(&s[2*q+0], lo);
        atomicAdd(&s[2*q+1], hi);
    }
}

// ---------------------------------------------------------------------------
// Kernel 2: fused z_q/loss (with on-the-fly EMA codebook) + one-hot + perplexity.
//   zq side:     1024 blocks, 8 elems/thread; each block replicates the nsum
//                reduce in the old statsemb's exact order, then computes
//                q = (0.99*ema_w + 0.01*g_sum)/csn per element (bit-identical
//                to the old g_emb value).
//   onehot side: 8192 blocks, 4 rows/block, contiguous 2KB streaming chunks.
//   All bulk output stores use __stcs (streaming, write-once data).
// ---------------------------------------------------------------------------
#define ZQB  (N_ELEM / 2048)        // 1024 zq blocks
#define OHB  (N_TOK / 4)            // 8192 onehot blocks
#define KD   0.00999999977648258209228515625f   // (float)(1.0 - 0.99)

__global__ __launch_bounds__(256)
void k_zq_onehot(const float* __restrict__ z,
                 const float* __restrict__ ema_cs,
                 const float* __restrict__ ema_w,
                 float* __restrict__ out) {
    const int tid = threadIdx.x;
    if (blockIdx.x < ZQB) {
        __shared__ float red[256];
        __shared__ float warpsum[8];

        // nsum: identical grouped-4 + tree order as the old k_statsemb
        float local = 0.f;
        #pragma unroll
        for (int k = 0; k < 4; ++k) {
            int j = tid * 4 + k;
            float ncs = __fadd_rn(__fmul_rn(DECAY, ema_cs[j]),
                                  __fmul_rn(KD, g_cs[j]));
            local = __fadd_rn(local, ncs);
        }
        red[tid] = local;
        __syncthreads();
        for (int s = 128; s > 0; s >>= 1) {
            if (tid < s) red[tid] = __fadd_rn(red[tid], red[tid + s]);
            __syncthreads();
        }
        const float nsum = red[0];
        const float dnorm = __fadd_rn(nsum, (float)N_E * EPSF);
        __syncthreads();

        int base = blockIdx.x * 2048 + tid;
        float acc = 0.f;
        #pragma unroll
        for (int k = 0; k < 8; ++k) {
            int i = base + k * 256;
            int hw = i & 1023;
            int c  = (i >> 10) & 63;
            int b  = i >> 16;
            int n  = (b << 10) | hw;
            int j  = g_idx[n];
            // on-the-fly EMA codebook entry (bit-identical to old g_emb[j*64+c])
            float ncs = __fadd_rn(__fmul_rn(DECAY, ema_cs[j]),
                                  __fmul_rn(KD, g_cs[j]));
            float csn = __fmul_rn(__fdiv_rn(__fadd_rn(ncs, EPSF), dnorm), nsum);
            int jc = j * E_DIM + c;
            float nw = __fadd_rn(__fmul_rn(DECAY, ema_w[jc]),
                                 __fmul_rn(KD, g_sum[jc]));
            float q  = __fdiv_rn(nw, csn);

            float zv = z[i];
            float dq = __fsub_rn(q, zv);
            __stcs(&out[O_ZQ + i], __fadd_rn(zv, dq));
            acc = __fadd_rn(acc, __fmul_rn(dq, dq));
        }
        #pragma unroll
        for (int s = 16; s > 0; s >>= 1)
            acc += __shfl_down_sync(0xffffffffu, acc, s);
        int lane = tid & 31, wid = tid >> 5;
        if (lane == 0) warpsum[wid] = acc;
        __syncthreads();
        if (wid == 0) {
            float v = (lane < 8) ? warpsum[lane] : 0.f;
            #pragma unroll
            for (int s = 4; s > 0; s >>= 1)
                v += __shfl_down_sync(0xffffffffu, v, s);
            if (lane == 0) {
                atomicAdd(&g_loss_acc, v);
                __threadfence();
                unsigned int done = atomicAdd(&g_done, 1u);
                if (done == ZQB - 1) {
                    out[O_LOSS] = __fmul_rn(BETA,
                                            __fdiv_rn(g_loss_acc, (float)N_ELEM));
                }
            }
        }

        // perplexity (block 0 only; identical order to old statsemb block 0)
        if (blockIdx.x == 0) {
            __syncthreads();
            float p = 0.f;
            #pragma unroll
            for (int k = 0; k < 4; ++k) {
                int jj = tid * 4 + k;
                float avg = g_cs[jj] * (1.0f / (float)N_TOK);
                p = __fadd_rn(p, __fmul_rn(avg, logf(__fadd_rn(avg, 1e-10f))));
            }
            red[tid] = p;
            __syncthreads();
            for (int s = 128; s > 0; s >>= 1) {
                if (tid < s) red[tid] = __fadd_rn(red[tid], red[tid + s]);
                __syncthreads();
            }
            if (tid == 0) out[O_PERP] = expf(-red[0]);
        }
    } else {
        int blk = blockIdx.x - ZQB;
        int n0 = blk * 4;                         // 4 tokens per block
        int i0 = g_idx[n0+0], i1 = g_idx[n0+1], i2 = g_idx[n0+2], i3 = g_idx[n0+3];
        float2* dst = reinterpret_cast<float2*>(out + O_MINENC) + (size_t)n0 * 512;
        #pragma unroll
        for (int it = 0; it < 8; ++it) {
            int row  = it >> 1;                   // 0..3
            int idx  = (row == 0) ? i0 : (row == 1) ? i1 : (row == 2) ? i2 : i3;
            int pos  = ((it & 1) << 8) + tid;     // 0..511 within row
            int c    = pos << 1;
            float2 v;
            v.x = (c     == idx) ? 1.0f : 0.0f;
            v.y = (c + 1 == idx) ? 1.0f : 0.0f;
            __stcs(&dst[row * 512 + pos], v);
        }
    }
}

// ---------------------------------------------------------------------------
extern "C" void kernel_launch(void* const* d_in, const int* in_sizes, int n_in,
                              void* d_out, int out_size) {
    const float* z      = (const float*)d_in[0];
    const float* emb_w  = (const float*)d_in[1];
    const float* ema_cs = (const float*)d_in[2];
    const float* ema_w  = (const float*)d_in[3];
    float* out = (float*)d_out;

    k_prep<<<(N_E + 255) / 256, 256>>>(emb_w);
    k_argmin<<<N_TOK / 128, 128>>>(z, emb_w, out);
    k_zq_onehot<<<ZQB + OHB, 256>>>(z, ema_cs, ema_w, out);
}